// round 10
// baseline (speedup 1.0000x reference)
#include <cuda_runtime.h>
#include <math.h>
#include <stdint.h>

// Problem constants
#define TDIM 4096          // B*S tokens
#define HDIM 1024          // hidden
#define EDIM 8             // experts
#define FDIM 2048          // ffn
#define KSEL 2             // top-k
#define NROWS (TDIM*KSEL)  // 8192 dispatch rows

// ==================== device scratch (allocation-free) ====================
__device__ uint32_t g_xc[(size_t)TDIM * HDIM];             // x as tf32 bits
__device__ uint32_t g_w1c[(size_t)EDIM * HDIM * 2 * FDIM]; // w_in as tf32 bits
__device__ uint32_t g_w2c[(size_t)EDIM * FDIM * HDIM];     // w_out as tf32 bits
__device__ uint32_t g_glu[(size_t)NROWS * FDIM];           // GLU acts, tf32 bits (list order)
__device__ float    g_pairs[(size_t)NROWS * HDIM];         // expert outputs per (token,slot)
__device__ int   g_eid[NROWS];
__device__ float g_gate[NROWS];
__device__ int   g_list[NROWS];
__device__ int   g_freq[EDIM];
__device__ int   g_cursor[EDIM];
__device__ int   g_offsets[EDIM + 1];
__device__ float g_psum[EDIM];
__device__ float g_lsesq;

// ==================== PTX helpers (sm_80-baseline features only) ====================
__device__ __forceinline__ uint32_t smem_u32(const void* p) {
    uint32_t a;
    asm("{ .reg .u64 t; cvta.to.shared.u64 t, %1; cvt.u32.u64 %0, t; }" : "=r"(a) : "l"(p));
    return a;
}
__device__ __forceinline__ void cp16(uint32_t dst, const void* src) {
    asm volatile("cp.async.cg.shared.global [%0], [%1], 16;" :: "r"(dst), "l"(src));
}
#define CP_COMMIT() asm volatile("cp.async.commit_group;" ::: "memory")
#define CP_WAIT1()  asm volatile("cp.async.wait_group 1;" ::: "memory")
#define CP_WAIT0()  asm volatile("cp.async.wait_group 0;" ::: "memory")

__device__ __forceinline__ uint32_t f2tf32(float f) {
    uint32_t r;
    asm("cvt.rna.tf32.f32 %0, %1;" : "=r"(r) : "f"(f));
    return r;
}
__device__ __forceinline__ void mma_tf32(float* d, const uint32_t* a, const uint32_t* b) {
    asm volatile(
        "mma.sync.aligned.m16n8k8.row.col.f32.tf32.tf32.f32 "
        "{%0,%1,%2,%3}, {%4,%5,%6,%7}, {%8,%9}, {%0,%1,%2,%3};"
        : "+f"(d[0]), "+f"(d[1]), "+f"(d[2]), "+f"(d[3])
        : "r"(a[0]), "r"(a[1]), "r"(a[2]), "r"(a[3]), "r"(b[0]), "r"(b[1]));
}

// Shared-memory tile geometry (padded, conflict-free)
#define ASTR 36     // A row stride (u32): bank = (4g+tq)%32 distinct
#define BSTR 136    // B row stride (u32): bank = (8tq+g)%32 distinct
#define MT 256      // CTA M-tile
#define SM_AS 1024                              // after s_tok[256]
#define SM_BS (SM_AS + 2*MT*ASTR*4)             // 1024 + 73728 = 74752
#define GEMM_SMEM (SM_BS + 2*32*BSTR*4)         // + 34816 = 109568

// ==================== reset counters (graph replays) ====================
__global__ void zero_kernel() {
    int i = threadIdx.x;
    if (i < EDIM) { g_freq[i] = 0; g_cursor[i] = 0; g_psum[i] = 0.f; }
    if (i == 0) g_lsesq = 0.f;
}

// ==================== tf32 pre-conversion ====================
__global__ void conv_kernel(const float4* __restrict__ src, uint4* __restrict__ dst, int n4) {
    int i = blockIdx.x * 256 + threadIdx.x;
    if (i < n4) {
        float4 v = src[i];
        uint4 o;
        o.x = f2tf32(v.x); o.y = f2tf32(v.y);
        o.z = f2tf32(v.z); o.w = f2tf32(v.w);
        dst[i] = o;
    }
}

// ==================== router ====================
__global__ void router_kernel(const float* __restrict__ x,
                              const float* __restrict__ wr) {
    __shared__ float s_p[EDIM];
    __shared__ float s_lsesq;
    int tid = threadIdx.x;
    if (tid < EDIM) s_p[tid] = 0.f;
    if (tid == 0) s_lsesq = 0.f;
    __syncthreads();

    int t = blockIdx.x * 8 + (tid >> 5);
    int lane = tid & 31;

    float acc[8] = {0.f,0.f,0.f,0.f,0.f,0.f,0.f,0.f};
    const float* xp = x + (size_t)t * HDIM;
    for (int h = lane; h < HDIM; h += 32) {
        float xv = xp[h];
        float4 w0 = *(const float4*)(wr + h * 8);
        float4 w1 = *(const float4*)(wr + h * 8 + 4);
        acc[0] += xv * w0.x; acc[1] += xv * w0.y;
        acc[2] += xv * w0.z; acc[3] += xv * w0.w;
        acc[4] += xv * w1.x; acc[5] += xv * w1.y;
        acc[6] += xv * w1.z; acc[7] += xv * w1.w;
    }
#pragma unroll
    for (int e = 0; e < 8; e++)
#pragma unroll
        for (int o = 16; o > 0; o >>= 1)
            acc[e] += __shfl_down_sync(0xffffffffu, acc[e], o);

    if (lane == 0) {
        float m = acc[0];
#pragma unroll
        for (int e = 1; e < 8; e++) m = fmaxf(m, acc[e]);
        float ex[8], sum = 0.f;
#pragma unroll
        for (int e = 0; e < 8; e++) { ex[e] = expf(acc[e] - m); sum += ex[e]; }
        float inv = 1.f / sum;
        float lse = m + logf(sum);

        int i0 = 0;
#pragma unroll
        for (int e = 1; e < 8; e++) if (acc[e] > acc[i0]) i0 = e;
        int i1 = (i0 == 0) ? 1 : 0;
#pragma unroll
        for (int e = 0; e < 8; e++) if (e != i0 && acc[e] > acc[i1]) i1 = e;

        float d = expf(acc[i1] - acc[i0]);
        float g0 = 1.f / (1.f + d);
        float g1 = d / (1.f + d);

        g_eid[2 * t]     = i0;  g_eid[2 * t + 1]  = i1;
        g_gate[2 * t]    = g0;  g_gate[2 * t + 1] = g1;
        atomicAdd(&g_freq[i0], 1);
        atomicAdd(&g_freq[i1], 1);
#pragma unroll
        for (int e = 0; e < 8; e++) atomicAdd(&s_p[e], ex[e] * inv);
        atomicAdd(&s_lsesq, lse * lse);
    }
    __syncthreads();
    if (tid < EDIM) atomicAdd(&g_psum[tid], s_p[tid]);
    if (tid == 0)   atomicAdd(&g_lsesq, s_lsesq);
}

__global__ void scan_kernel() {
    if (threadIdx.x == 0) {
        int s = 0;
        for (int e = 0; e < EDIM; e++) { g_offsets[e] = s; s += g_freq[e]; }
        g_offsets[EDIM] = s;
    }
}

__global__ void scatter_kernel() {
    int r = blockIdx.x * blockDim.x + threadIdx.x;
    if (r < NROWS) {
        int e = g_eid[r];
        int pos = atomicAdd(&g_cursor[e], 1);
        g_list[g_offsets[e] + pos] = r;
    }
}

// ==================== tile loaders (256 threads) ====================
// A: MT gathered rows x 32 K-u32. B: 32 K-rows x 128 cols.
__device__ __forceinline__ void g1_load(const uint32_t* __restrict__ w1,
                                        const int* s_tok,
                                        uint32_t as_u, uint32_t bs_u,
                                        int tid, int n0, int c, int st) {
    const int k0 = c * 32;
#pragma unroll
    for (int i = 0; i < 8; i++) {                  // 2048 16B-chunks / 256 thr
        int idx = tid + i * 256;
        int row = idx >> 3, seg = idx & 7;
        const uint32_t* src = g_xc + (size_t)s_tok[row] * HDIM + k0 + seg * 4;
        cp16(as_u + (uint32_t)((st * MT * ASTR + row * ASTR + seg * 4) * 4), src);
    }
#pragma unroll
    for (int i = 0; i < 4; i++) {                  // 1024 chunks / 256 thr
        int idx = tid + i * 256;
        int kr = idx >> 5, j = (idx & 31) * 4;
        int half = (j >> 5) & 1, blk = j >> 6, cloc = j & 31;
        int wcol = n0 + blk * 32 + cloc + (half ? FDIM : 0);
        const uint32_t* src = w1 + (size_t)(k0 + kr) * (2 * FDIM) + wcol;
        cp16(bs_u + (uint32_t)((st * 32 * BSTR + kr * BSTR + j) * 4), src);
    }
    CP_COMMIT();
}

__device__ __forceinline__ void g2_load(const uint32_t* __restrict__ w2,
                                        int off, int row0, int rlim,
                                        uint32_t as_u, uint32_t bs_u,
                                        int tid, int n1, int c, int st) {
    const int k0 = c * 32;
#pragma unroll
    for (int i = 0; i < 8; i++) {
        int idx = tid + i * 256;
        int row = idx >> 3, seg = idx & 7;
        int rr = (row < rlim) ? row : (rlim - 1);
        const uint32_t* src = g_glu + (size_t)(off + row0 + rr) * FDIM + k0 + seg * 4;
        cp16(as_u + (uint32_t)((st * MT * ASTR + row * ASTR + seg * 4) * 4), src);
    }
#pragma unroll
    for (int i = 0; i < 4; i++) {
        int idx = tid + i * 256;
        int kr = idx >> 5, j = (idx & 31) * 4;
        const uint32_t* src = w2 + (size_t)(k0 + kr) * HDIM + n1 + j;
        cp16(bs_u + (uint32_t)((st * 32 * BSTR + kr * BSTR + j) * 4), src);
    }
    CP_COMMIT();
}

// ==================== GEMM1: x[tok] @ w_in[e], fused GLU ====================
// CTA tile 256 rows x (64 a-cols + 64 gv-cols). 8 warps of 64x64.
__global__ void __launch_bounds__(256) gemm1_mma(const uint32_t* __restrict__ w_in_c) {
    const int e = blockIdx.z;
    const int cnt = g_freq[e];
    const int row0 = blockIdx.y * MT;
    if (row0 >= cnt) return;
    const int off = g_offsets[e];
    const int n0 = blockIdx.x * 64;

    extern __shared__ char smem[];
    int* s_tok = (int*)smem;
    uint32_t* As = (uint32_t*)(smem + SM_AS);
    uint32_t* Bs = (uint32_t*)(smem + SM_BS);
    const uint32_t as_u = smem_u32(As), bs_u = smem_u32(Bs);

    const int tid = threadIdx.x;
    {
        int r = row0 + tid;
        s_tok[tid] = g_list[off + ((r < cnt) ? r : (cnt - 1))] >> 1;
    }
    __syncthreads();

    const uint32_t* w1 = w_in_c + (size_t)e * HDIM * (2 * FDIM);

    const int lane = tid & 31, wid = tid >> 5;
    const int wm = wid & 3, wn = wid >> 2;
    const int g = lane >> 2, tq = lane & 3;

    float acc[4][8][4];
#pragma unroll
    for (int i = 0; i < 4; i++)
#pragma unroll
        for (int f = 0; f < 8; f++)
#pragma unroll
            for (int q = 0; q < 4; q++) acc[i][f][q] = 0.f;

    const int NCH = HDIM / 32;  // 32
    g1_load(w1, s_tok, as_u, bs_u, tid, n0, 0, 0);
    g1_load(w1, s_tok, as_u, bs_u, tid, n0, 1, 1);
    CP_WAIT1();
    __syncthreads();

    for (int c = 0; c < NCH; c++) {
        const int st = c & 1;
        const uint32_t* Ast = As + st * MT * ASTR;
        const uint32_t* Bst = Bs + st * 32 * BSTR;
#pragma unroll
        for (int ks = 0; ks < 4; ks++) {
            uint32_t af[4][4];
#pragma unroll
            for (int i = 0; i < 4; i++) {
                const uint32_t* ap = Ast + (wm * 64 + i * 16 + g) * ASTR + ks * 8 + tq;
                af[i][0] = ap[0];
                af[i][1] = ap[8 * ASTR];
                af[i][2] = ap[4];
                af[i][3] = ap[8 * ASTR + 4];
            }
            uint32_t bf[8][2];
#pragma unroll
            for (int f = 0; f < 8; f++) {
                const uint32_t* bp = Bst + (ks * 8 + tq) * BSTR + wn * 64 + f * 8 + g;
                bf[f][0] = bp[0];
                bf[f][1] = bp[4 * BSTR];
            }
#pragma unroll
            for (int i = 0; i < 4; i++)
#pragma unroll
                for (int f = 0; f < 8; f++)
                    mma_tf32(acc[i][f], af[i], bf[f]);
        }
        __syncthreads();
        if (c + 2 < NCH) g1_load(w1, s_tok, as_u, bs_u, tid, n0, c + 2, st);
        if (c + 1 < NCH) {
            if (c + 2 < NCH) CP_WAIT1(); else CP_WAIT0();
            __syncthreads();
        }
    }

    // epilogue: GLU; store tf32-rounded bits (GEMM2 consumes raw)
#pragma unroll
    for (int i = 0; i < 4; i++) {
        const int rbase = wm * 64 + i * 16 + g;
#pragma unroll
        for (int hr = 0; hr < 2; hr++) {
            const int r = rbase + hr * 8;
            if (row0 + r < cnt) {
                uint32_t* dst = g_glu + (size_t)(off + row0 + r) * FDIM + n0 + wn * 32;
#pragma unroll
                for (int f = 0; f < 4; f++) {
                    float a0 = acc[i][f][hr * 2], a1 = acc[i][f][hr * 2 + 1];
                    float v0 = acc[i][f + 4][hr * 2], v1 = acc[i][f + 4][hr * 2 + 1];
                    uint2 o;
                    o.x = f2tf32((a0 / (1.f + __expf(-a0))) * v0);
                    o.y = f2tf32((a1 / (1.f + __expf(-a1))) * v1);
                    *(uint2*)(dst + f * 8 + 2 * tq) = o;
                }
            }
        }
    }
}

// ==================== GEMM2: glu @ w_out[e], fused gate-scale scatter ====================
__global__ void __launch_bounds__(256) gemm2_mma(const uint32_t* __restrict__ w_out_c) {
    const int e = blockIdx.z;
    const int cnt = g_freq[e];
    const int row0 = blockIdx.y * MT;
    if (row0 >= cnt) return;
    const int off = g_offsets[e];
    const int n1 = blockIdx.x * 128;
    const int rlim = cnt - row0;

    extern __shared__ char smem[];
    int* s_dst = (int*)smem;
    uint32_t* As = (uint32_t*)(smem + SM_AS);
    uint32_t* Bs = (uint32_t*)(smem + SM_BS);
    const uint32_t as_u = smem_u32(As), bs_u = smem_u32(Bs);

    const int tid = threadIdx.x;
    {
        int r = row0 + tid;
        s_dst[tid] = g_list[off + ((r < cnt) ? r : (cnt - 1))];
    }
    __syncthreads();

    const uint32_t* w2 = w_out_c + (size_t)e * FDIM * HDIM;

    const int lane = tid & 31, wid = tid >> 5;
    const int wm = wid & 3, wn = wid >> 2;
    const int g = lane >> 2, tq = lane & 3;

    float acc[4][8][4];
#pragma unroll
    for (int i = 0; i < 4; i++)
#pragma unroll
        for (int f = 0; f < 8; f++)
#pragma unroll
            for (int q = 0; q < 4; q++) acc[i][f][q] = 0.f;

    const int NCH = FDIM / 32;  // 64
    g2_load(w2, off, row0, rlim, as_u, bs_u, tid, n1, 0, 0);
    g2_load(w2, off, row0, rlim, as_u, bs_u, tid, n1, 1, 1);
    CP_WAIT1();
    __syncthreads();

    for (int c = 0; c < NCH; c++) {
        const int st = c & 1;
        const uint32_t* Ast = As + st * MT * ASTR;
        const uint32_t* Bst = Bs + st * 32 * BSTR;
#pragma unroll
        for (int ks = 0; ks < 4; ks++) {
            uint32_t af[4][4];
#pragma unroll
            for (int i = 0; i < 4; i++) {
                const uint32_t* ap = Ast + (wm * 64 + i * 16 + g) * ASTR + ks * 8 + tq;
                af[i][0] = ap[0];
                af[i][1] = ap[8 * ASTR];
                af[i][2] = ap[4];
                af[i][3] = ap[8 * ASTR + 4];
            }
            uint32_t bf[8][2];
#pragma unroll
            for (int f = 0; f < 8; f++) {
                const uint32_t* bp = Bst + (ks * 8 + tq) * BSTR + wn * 64 + f * 8 + g;
                bf[f][0] = bp[0];
                bf[f][1] = bp[4 * BSTR];
            }
#pragma unroll
            for (int i = 0; i < 4; i++)
#pragma unroll
                for (int f = 0; f < 8; f++)
                    mma_tf32(acc[i][f], af[i], bf[f]);
        }
        __syncthreads();
        if (c + 2 < NCH) g2_load(w2, off, row0, rlim, as_u, bs_u, tid, n1, c + 2, st);
        if (c + 1 < NCH) {
            if (c + 2 < NCH) CP_WAIT1(); else CP_WAIT0();
            __syncthreads();
        }
    }

    // epilogue: scale by gate, scatter rows to g_pairs[dst]
#pragma unroll
    for (int i = 0; i < 4; i++) {
        const int rbase = wm * 64 + i * 16 + g;
#pragma unroll
        for (int hr = 0; hr < 2; hr++) {
            const int r = rbase + hr * 8;
            if (r < rlim) {
                const int dst = s_dst[r];
                const float gt = g_gate[dst];
                float* op = g_pairs + (size_t)dst * HDIM + n1 + wn * 64;
#pragma unroll
                for (int f = 0; f < 8; f++) {
                    float2 o;
                    o.x = acc[i][f][hr * 2] * gt;
                    o.y = acc[i][f][hr * 2 + 1] * gt;
                    *(float2*)(op + f * 8 + 2 * tq) = o;
                }
            }
        }
    }
}

// ==================== combine + loss ====================
__global__ void combine_kernel(float* __restrict__ out, const float* __restrict__ bias) {
    int i = blockIdx.x * blockDim.x + threadIdx.x;
    if (i < TDIM * HDIM / 4) {
        int t = i >> 8;
        int c4 = i & 255;
        const float4* p4 = (const float4*)g_pairs;
        float4 a = p4[(size_t)(2 * t) * 256 + c4];
        float4 b = p4[(size_t)(2 * t) * 256 + 256 + c4];
        float4 bs = ((const float4*)bias)[c4];
        float4 o;
        o.x = a.x + b.x + bs.x; o.y = a.y + b.y + bs.y;
        o.z = a.z + b.z + bs.z; o.w = a.w + b.w + bs.w;
        ((float4*)out)[i] = o;
    }
}

__global__ void loss_kernel(float* __restrict__ out, int out_size) {
    if (threadIdx.x == 0 && blockIdx.x == 0) {
        float s = 0.f;
        for (int e = 0; e < EDIM; e++) s += g_psum[e] * (float)g_freq[e];
        float loss = (float)EDIM * s / ((float)TDIM * (float)(TDIM * KSEL))
                   + 0.1f * g_lsesq / (float)TDIM;
        if (out_size > TDIM * HDIM) out[TDIM * HDIM] = loss;
    }
}

// ==================== launch ====================
extern "C" void kernel_launch(void* const* d_in, const int* in_sizes, int n_in,
                              void* d_out, int out_size) {
    const float* x        = (const float*)d_in[0];
    const float* w_router = (const float*)d_in[1];
    const float* w_in     = (const float*)d_in[2];
    const float* w_out    = (const float*)d_in[3];
    const float* bias     = (const float*)d_in[4];
    float* out = (float*)d_out;

    cudaFuncSetAttribute(gemm1_mma, cudaFuncAttributeMaxDynamicSharedMemorySize, GEMM_SMEM);
    cudaFuncSetAttribute(gemm2_mma, cudaFuncAttributeMaxDynamicSharedMemorySize, GEMM_SMEM);

    // resolve device-scratch addresses for conversion outputs
    uint32_t *xc_p, *w1c_p, *w2c_p;
    cudaGetSymbolAddress((void**)&xc_p, g_xc);
    cudaGetSymbolAddress((void**)&w1c_p, g_w1c);
    cudaGetSymbolAddress((void**)&w2c_p, g_w2c);

    zero_kernel<<<1, 32>>>();

    // tf32 pre-conversion (one rounding, reused everywhere)
    {
        int n4x = TDIM * HDIM / 4;
        conv_kernel<<<(n4x + 255) / 256, 256>>>((const float4*)x, (uint4*)xc_p, n4x);
        int n4w1 = EDIM * HDIM * 2 * FDIM / 4;
        conv_kernel<<<(n4w1 + 255) / 256, 256>>>((const float4*)w_in, (uint4*)w1c_p, n4w1);
        int n4w2 = EDIM * FDIM * HDIM / 4;
        conv_kernel<<<(n4w2 + 255) / 256, 256>>>((const float4*)w_out, (uint4*)w2c_p, n4w2);
    }

    router_kernel<<<TDIM / 8, 256>>>(x, w_router);
    scan_kernel<<<1, 32>>>();
    scatter_kernel<<<NROWS / 256, 256>>>();

    gemm1_mma<<<dim3(FDIM / 64, TDIM / MT, EDIM), 256, GEMM_SMEM>>>(w1c_p);
    gemm2_mma<<<dim3(HDIM / 128, TDIM / MT, EDIM), 256, GEMM_SMEM>>>(w2c_p);

    combine_kernel<<<(TDIM * HDIM / 4 + 255) / 256, 256>>>(out, bias);
    loss_kernel<<<1, 32>>>(out, out_size);
}

// round 11
// speedup vs baseline: 1.0680x; 1.0680x over previous
#include <cuda_runtime.h>
#include <math.h>
#include <stdint.h>

// Problem constants
#define TDIM 4096          // B*S tokens
#define HDIM 1024          // hidden
#define EDIM 8             // experts
#define FDIM 2048          // ffn
#define KSEL 2             // top-k
#define NROWS (TDIM*KSEL)  // 8192 dispatch rows

// ==================== device scratch (allocation-free) ====================
__device__ float g_glu[(size_t)NROWS * FDIM];    // GLU activations (list order)
__device__ float g_pairs[(size_t)NROWS * HDIM];  // expert outputs per (token,slot)
__device__ int   g_eid[NROWS];
__device__ float g_gate[NROWS];
__device__ int   g_list[NROWS];
__device__ int   g_freq[EDIM];
__device__ int   g_cursor[EDIM];
__device__ int   g_offsets[EDIM + 1];
__device__ float g_psum[EDIM];
__device__ float g_lsesq;

// ==================== PTX helpers (sm_80-baseline features only) ====================
__device__ __forceinline__ uint32_t smem_u32(const void* p) {
    uint32_t a;
    asm("{ .reg .u64 t; cvta.to.shared.u64 t, %1; cvt.u32.u64 %0, t; }" : "=r"(a) : "l"(p));
    return a;
}
__device__ __forceinline__ void cp16(uint32_t dst, const void* src) {
    asm volatile("cp.async.cg.shared.global [%0], [%1], 16;" :: "r"(dst), "l"(src));
}
#define CP_COMMIT() asm volatile("cp.async.commit_group;" ::: "memory")
#define CP_WAIT1()  asm volatile("cp.async.wait_group 1;" ::: "memory")
#define CP_WAIT0()  asm volatile("cp.async.wait_group 0;" ::: "memory")

__device__ __forceinline__ uint32_t f2tf32(float f) {
    uint32_t r;
    asm("cvt.rna.tf32.f32 %0, %1;" : "=r"(r) : "f"(f));
    return r;
}
__device__ __forceinline__ void mma_tf32(float* d, const uint32_t* a, const uint32_t* b) {
    asm volatile(
        "mma.sync.aligned.m16n8k8.row.col.f32.tf32.tf32.f32 "
        "{%0,%1,%2,%3}, {%4,%5,%6,%7}, {%8,%9}, {%0,%1,%2,%3};"
        : "+f"(d[0]), "+f"(d[1]), "+f"(d[2]), "+f"(d[3])
        : "r"(a[0]), "r"(a[1]), "r"(a[2]), "r"(a[3]), "r"(b[0]), "r"(b[1]));
}

// Shared-memory tile geometry (padded, conflict-free)
#define ASTR 36     // A row stride (floats): bank = (4g+tq)%32 distinct
#define BSTR 136    // B row stride (floats): bank = (8tq+g)%32 distinct
#define NSTAGE 3
#define A_STG (128*ASTR)            // floats per A stage
#define B_STG (32*BSTR)             // floats per B stage
#define SM_AS 512                                   // after s_tok[128]
#define SM_BS (SM_AS + NSTAGE*A_STG*4)              // 512 + 55296 = 55808
#define GEMM_SMEM (SM_BS + NSTAGE*B_STG*4)          // + 52224 = 108032

// ==================== reset counters (graph replays) ====================
__global__ void zero_kernel() {
    int i = threadIdx.x;
    if (i < EDIM) { g_freq[i] = 0; g_cursor[i] = 0; g_psum[i] = 0.f; }
    if (i == 0) g_lsesq = 0.f;
}

// ==================== router ====================
__global__ void router_kernel(const float* __restrict__ x,
                              const float* __restrict__ wr) {
    __shared__ float s_p[EDIM];
    __shared__ float s_lsesq;
    int tid = threadIdx.x;
    if (tid < EDIM) s_p[tid] = 0.f;
    if (tid == 0) s_lsesq = 0.f;
    __syncthreads();

    int t = blockIdx.x * 8 + (tid >> 5);
    int lane = tid & 31;

    float acc[8] = {0.f,0.f,0.f,0.f,0.f,0.f,0.f,0.f};
    const float* xp = x + (size_t)t * HDIM;
    for (int h = lane; h < HDIM; h += 32) {
        float xv = xp[h];
        float4 w0 = *(const float4*)(wr + h * 8);
        float4 w1 = *(const float4*)(wr + h * 8 + 4);
        acc[0] += xv * w0.x; acc[1] += xv * w0.y;
        acc[2] += xv * w0.z; acc[3] += xv * w0.w;
        acc[4] += xv * w1.x; acc[5] += xv * w1.y;
        acc[6] += xv * w1.z; acc[7] += xv * w1.w;
    }
#pragma unroll
    for (int e = 0; e < 8; e++)
#pragma unroll
        for (int o = 16; o > 0; o >>= 1)
            acc[e] += __shfl_down_sync(0xffffffffu, acc[e], o);

    if (lane == 0) {
        float m = acc[0];
#pragma unroll
        for (int e = 1; e < 8; e++) m = fmaxf(m, acc[e]);
        float ex[8], sum = 0.f;
#pragma unroll
        for (int e = 0; e < 8; e++) { ex[e] = expf(acc[e] - m); sum += ex[e]; }
        float inv = 1.f / sum;
        float lse = m + logf(sum);

        int i0 = 0;
#pragma unroll
        for (int e = 1; e < 8; e++) if (acc[e] > acc[i0]) i0 = e;
        int i1 = (i0 == 0) ? 1 : 0;
#pragma unroll
        for (int e = 0; e < 8; e++) if (e != i0 && acc[e] > acc[i1]) i1 = e;

        float d = expf(acc[i1] - acc[i0]);
        float g0 = 1.f / (1.f + d);
        float g1 = d / (1.f + d);

        g_eid[2 * t]     = i0;  g_eid[2 * t + 1]  = i1;
        g_gate[2 * t]    = g0;  g_gate[2 * t + 1] = g1;
        atomicAdd(&g_freq[i0], 1);
        atomicAdd(&g_freq[i1], 1);
#pragma unroll
        for (int e = 0; e < 8; e++) atomicAdd(&s_p[e], ex[e] * inv);
        atomicAdd(&s_lsesq, lse * lse);
    }
    __syncthreads();
    if (tid < EDIM) atomicAdd(&g_psum[tid], s_p[tid]);
    if (tid == 0)   atomicAdd(&g_lsesq, s_lsesq);
}

__global__ void scan_kernel() {
    if (threadIdx.x == 0) {
        int s = 0;
        for (int e = 0; e < EDIM; e++) { g_offsets[e] = s; s += g_freq[e]; }
        g_offsets[EDIM] = s;
    }
}

__global__ void scatter_kernel() {
    int r = blockIdx.x * blockDim.x + threadIdx.x;
    if (r < NROWS) {
        int e = g_eid[r];
        int pos = atomicAdd(&g_cursor[e], 1);
        g_list[g_offsets[e] + pos] = r;
    }
}

// ==================== tile loaders (128 threads) ====================
// A: 128 gathered rows x 32 K-floats. B: 32 K-rows x 128 cols.
__device__ __forceinline__ void g1_load(const float* __restrict__ x,
                                        const float* __restrict__ w1,
                                        const int* s_tok,
                                        uint32_t as_u, uint32_t bs_u,
                                        int tid, int n0, int c) {
    const int k0 = c * 32;
    const int st = c % NSTAGE;
#pragma unroll
    for (int i = 0; i < 8; i++) {
        int idx = tid + i * 128;
        int row = idx >> 3, seg = idx & 7;
        const float* src = x + (size_t)s_tok[row] * HDIM + k0 + seg * 4;
        cp16(as_u + (uint32_t)((st * A_STG + row * ASTR + seg * 4) * 4), src);
    }
#pragma unroll
    for (int i = 0; i < 8; i++) {
        int idx = tid + i * 128;
        int kr = idx >> 5, j = (idx & 31) * 4;
        int half = (j >> 5) & 1, blk = j >> 6, cloc = j & 31;
        int wcol = n0 + blk * 32 + cloc + (half ? FDIM : 0);
        const float* src = w1 + (size_t)(k0 + kr) * (2 * FDIM) + wcol;
        cp16(bs_u + (uint32_t)((st * B_STG + kr * BSTR + j) * 4), src);
    }
    CP_COMMIT();
}

__device__ __forceinline__ void g2_load(const float* __restrict__ w2,
                                        int off, int row0, int rlim,
                                        uint32_t as_u, uint32_t bs_u,
                                        int tid, int n1, int c) {
    const int k0 = c * 32;
    const int st = c % NSTAGE;
#pragma unroll
    for (int i = 0; i < 8; i++) {
        int idx = tid + i * 128;
        int row = idx >> 3, seg = idx & 7;
        int rr = (row < rlim) ? row : (rlim - 1);
        const float* src = g_glu + (size_t)(off + row0 + rr) * FDIM + k0 + seg * 4;
        cp16(as_u + (uint32_t)((st * A_STG + row * ASTR + seg * 4) * 4), src);
    }
#pragma unroll
    for (int i = 0; i < 8; i++) {
        int idx = tid + i * 128;
        int kr = idx >> 5, j = (idx & 31) * 4;
        const float* src = w2 + (size_t)(k0 + kr) * HDIM + n1 + j;
        cp16(bs_u + (uint32_t)((st * B_STG + kr * BSTR + j) * 4), src);
    }
    CP_COMMIT();
}

// compute one K-chunk (shared by both GEMMs)
__device__ __forceinline__ void chunk_mma(const float* Ast, const float* Bst,
                                          int wm, int wn, int g, int tq,
                                          float acc[4][8][4]) {
#pragma unroll
    for (int ks = 0; ks < 4; ks++) {
        uint32_t af[4][4];
#pragma unroll
        for (int i = 0; i < 4; i++) {
            const float* ap = Ast + (wm * 64 + i * 16 + g) * ASTR + ks * 8 + tq;
            af[i][0] = f2tf32(ap[0]);
            af[i][1] = f2tf32(ap[8 * ASTR]);
            af[i][2] = f2tf32(ap[4]);
            af[i][3] = f2tf32(ap[8 * ASTR + 4]);
        }
        uint32_t bf[8][2];
#pragma unroll
        for (int f = 0; f < 8; f++) {
            const float* bp = Bst + (ks * 8 + tq) * BSTR + wn * 64 + f * 8 + g;
            bf[f][0] = f2tf32(bp[0]);
            bf[f][1] = f2tf32(bp[4 * BSTR]);
        }
#pragma unroll
        for (int i = 0; i < 4; i++)
#pragma unroll
            for (int f = 0; f < 8; f++)
                mma_tf32(acc[i][f], af[i], bf[f]);
    }
}

// ==================== GEMM1: x[tok] @ w_in[e], fused GLU ====================
// CTA tile 128 rows x (64 a-cols + 64 gv-cols). 4 warps of 64x64.
// 3-stage cp.async pipeline, ONE barrier per chunk, loads issued before compute.
__global__ void __launch_bounds__(128) gemm1_mma(const float* __restrict__ x,
                                                 const float* __restrict__ w_in) {
    const int e = blockIdx.z;
    const int cnt = g_freq[e];
    const int row0 = blockIdx.y * 128;
    if (row0 >= cnt) return;
    const int off = g_offsets[e];
    const int n0 = blockIdx.x * 64;

    extern __shared__ char smem[];
    int* s_tok = (int*)smem;
    float* As = (float*)(smem + SM_AS);
    float* Bs = (float*)(smem + SM_BS);
    const uint32_t as_u = smem_u32(As), bs_u = smem_u32(Bs);

    const int tid = threadIdx.x;
    {
        int r = row0 + tid;
        s_tok[tid] = g_list[off + ((r < cnt) ? r : (cnt - 1))] >> 1;
    }
    __syncthreads();

    const float* w1 = w_in + (size_t)e * HDIM * (2 * FDIM);

    const int lane = tid & 31, wid = tid >> 5;
    const int wm = wid & 1, wn = wid >> 1;
    const int g = lane >> 2, tq = lane & 3;

    float acc[4][8][4];
#pragma unroll
    for (int i = 0; i < 4; i++)
#pragma unroll
        for (int f = 0; f < 8; f++)
#pragma unroll
            for (int q = 0; q < 4; q++) acc[i][f][q] = 0.f;

    const int NCH = HDIM / 32;  // 32
    g1_load(x, w1, s_tok, as_u, bs_u, tid, n0, 0);
    g1_load(x, w1, s_tok, as_u, bs_u, tid, n0, 1);

    for (int c = 0; c < NCH; c++) {
        if (c + 1 < NCH) CP_WAIT1(); else CP_WAIT0();   // stage c arrived
        __syncthreads();                                 // buffer (c+2)%3 free
        if (c + 2 < NCH) g1_load(x, w1, s_tok, as_u, bs_u, tid, n0, c + 2);
        const int st = c % NSTAGE;
        chunk_mma(As + st * A_STG, Bs + st * B_STG, wm, wn, g, tq, acc);
    }

    // epilogue: GLU
#pragma unroll
    for (int i = 0; i < 4; i++) {
        const int rbase = wm * 64 + i * 16 + g;
#pragma unroll
        for (int hr = 0; hr < 2; hr++) {
            const int r = rbase + hr * 8;
            if (row0 + r < cnt) {
                float* dst = g_glu + (size_t)(off + row0 + r) * FDIM + n0 + wn * 32;
#pragma unroll
                for (int f = 0; f < 4; f++) {
                    float a0 = acc[i][f][hr * 2], a1 = acc[i][f][hr * 2 + 1];
                    float v0 = acc[i][f + 4][hr * 2], v1 = acc[i][f + 4][hr * 2 + 1];
                    float2 o;
                    o.x = (a0 / (1.f + __expf(-a0))) * v0;
                    o.y = (a1 / (1.f + __expf(-a1))) * v1;
                    *(float2*)(dst + f * 8 + 2 * tq) = o;
                }
            }
        }
    }
}

// ==================== GEMM2: glu @ w_out[e], fused gate-scale scatter ====================
__global__ void __launch_bounds__(128) gemm2_mma(const float* __restrict__ w_out) {
    const int e = blockIdx.z;
    const int cnt = g_freq[e];
    const int row0 = blockIdx.y * 128;
    if (row0 >= cnt) return;
    const int off = g_offsets[e];
    const int n1 = blockIdx.x * 128;
    const int rlim = cnt - row0;

    extern __shared__ char smem[];
    int* s_dst = (int*)smem;
    float* As = (float*)(smem + SM_AS);
    float* Bs = (float*)(smem + SM_BS);
    const uint32_t as_u = smem_u32(As), bs_u = smem_u32(Bs);

    const int tid = threadIdx.x;
    {
        int r = row0 + tid;
        s_dst[tid] = g_list[off + ((r < cnt) ? r : (cnt - 1))];
    }
    __syncthreads();

    const float* w2 = w_out + (size_t)e * FDIM * HDIM;

    const int lane = tid & 31, wid = tid >> 5;
    const int wm = wid & 1, wn = wid >> 1;
    const int g = lane >> 2, tq = lane & 3;

    float acc[4][8][4];
#pragma unroll
    for (int i = 0; i < 4; i++)
#pragma unroll
        for (int f = 0; f < 8; f++)
#pragma unroll
            for (int q = 0; q < 4; q++) acc[i][f][q] = 0.f;

    const int NCH = FDIM / 32;  // 64
    g2_load(w2, off, row0, rlim, as_u, bs_u, tid, n1, 0);
    g2_load(w2, off, row0, rlim, as_u, bs_u, tid, n1, 1);

    for (int c = 0; c < NCH; c++) {
        if (c + 1 < NCH) CP_WAIT1(); else CP_WAIT0();
        __syncthreads();
        if (c + 2 < NCH) g2_load(w2, off, row0, rlim, as_u, bs_u, tid, n1, c + 2);
        const int st = c % NSTAGE;
        chunk_mma(As + st * A_STG, Bs + st * B_STG, wm, wn, g, tq, acc);
    }

    // epilogue: scale by gate, scatter rows to g_pairs[dst]
#pragma unroll
    for (int i = 0; i < 4; i++) {
        const int rbase = wm * 64 + i * 16 + g;
#pragma unroll
        for (int hr = 0; hr < 2; hr++) {
            const int r = rbase + hr * 8;
            if (r < rlim) {
                const int dst = s_dst[r];
                const float gt = g_gate[dst];
                float* op = g_pairs + (size_t)dst * HDIM + n1 + wn * 64;
#pragma unroll
                for (int f = 0; f < 8; f++) {
                    float2 o;
                    o.x = acc[i][f][hr * 2] * gt;
                    o.y = acc[i][f][hr * 2 + 1] * gt;
                    *(float2*)(op + f * 8 + 2 * tq) = o;
                }
            }
        }
    }
}

// ==================== combine + loss ====================
__global__ void combine_kernel(float* __restrict__ out, const float* __restrict__ bias) {
    int i = blockIdx.x * blockDim.x + threadIdx.x;
    if (i < TDIM * HDIM / 4) {
        int t = i >> 8;
        int c4 = i & 255;
        const float4* p4 = (const float4*)g_pairs;
        float4 a = p4[(size_t)(2 * t) * 256 + c4];
        float4 b = p4[(size_t)(2 * t) * 256 + 256 + c4];
        float4 bs = ((const float4*)bias)[c4];
        float4 o;
        o.x = a.x + b.x + bs.x; o.y = a.y + b.y + bs.y;
        o.z = a.z + b.z + bs.z; o.w = a.w + b.w + bs.w;
        ((float4*)out)[i] = o;
    }
}

__global__ void loss_kernel(float* __restrict__ out, int out_size) {
    if (threadIdx.x == 0 && blockIdx.x == 0) {
        float s = 0.f;
        for (int e = 0; e < EDIM; e++) s += g_psum[e] * (float)g_freq[e];
        float loss = (float)EDIM * s / ((float)TDIM * (float)(TDIM * KSEL))
                   + 0.1f * g_lsesq / (float)TDIM;
        if (out_size > TDIM * HDIM) out[TDIM * HDIM] = loss;
    }
}

// ==================== launch ====================
extern "C" void kernel_launch(void* const* d_in, const int* in_sizes, int n_in,
                              void* d_out, int out_size) {
    const float* x        = (const float*)d_in[0];
    const float* w_router = (const float*)d_in[1];
    const float* w_in     = (const float*)d_in[2];
    const float* w_out    = (const float*)d_in[3];
    const float* bias     = (const float*)d_in[4];
    float* out = (float*)d_out;

    cudaFuncSetAttribute(gemm1_mma, cudaFuncAttributeMaxDynamicSharedMemorySize, GEMM_SMEM);
    cudaFuncSetAttribute(gemm2_mma, cudaFuncAttributeMaxDynamicSharedMemorySize, GEMM_SMEM);

    zero_kernel<<<1, 32>>>();
    router_kernel<<<TDIM / 8, 256>>>(x, w_router);
    scan_kernel<<<1, 32>>>();
    scatter_kernel<<<NROWS / 256, 256>>>();

    gemm1_mma<<<dim3(FDIM / 64, TDIM / 128, EDIM), 128, GEMM_SMEM>>>(x, w_in);
    gemm2_mma<<<dim3(HDIM / 128, TDIM / 128, EDIM), 128, GEMM_SMEM>>>(w_out);

    combine_kernel<<<(TDIM * HDIM / 4 + 255) / 256, 256>>>(out, bias);
    loss_kernel<<<1, 32>>>(out, out_size);
}

// round 12
// speedup vs baseline: 1.2251x; 1.1471x over previous
#include <cuda_runtime.h>
#include <math.h>
#include <stdint.h>

// Problem constants
#define TDIM 4096          // B*S tokens
#define HDIM 1024          // hidden
#define EDIM 8             // experts
#define FDIM 2048          // ffn
#define KSEL 2             // top-k
#define NROWS (TDIM*KSEL)  // 8192 dispatch rows

// ==================== device scratch (allocation-free) ====================
__device__ float g_glu[(size_t)NROWS * FDIM];    // GLU activations (list order)
__device__ float g_pairs[(size_t)NROWS * HDIM];  // expert outputs per (token,slot)
__device__ int   g_eid[NROWS];
__device__ float g_gate[NROWS];
__device__ int   g_list[NROWS];
__device__ int   g_freq[EDIM];
__device__ int   g_cursor[EDIM];
__device__ int   g_offsets[EDIM + 1];
__device__ float g_psum[EDIM];
__device__ float g_lsesq;

// ==================== PTX helpers (sm_80-baseline features only) ====================
__device__ __forceinline__ uint32_t smem_u32(const void* p) {
    uint32_t a;
    asm("{ .reg .u64 t; cvta.to.shared.u64 t, %1; cvt.u32.u64 %0, t; }" : "=r"(a) : "l"(p));
    return a;
}
__device__ __forceinline__ void cp16(uint32_t dst, const void* src) {
    asm volatile("cp.async.cg.shared.global [%0], [%1], 16;" :: "r"(dst), "l"(src));
}
#define CP_COMMIT() asm volatile("cp.async.commit_group;" ::: "memory")
#define CP_WAIT1()  asm volatile("cp.async.wait_group 1;" ::: "memory")
#define CP_WAIT0()  asm volatile("cp.async.wait_group 0;" ::: "memory")

__device__ __forceinline__ uint32_t f2tf32(float f) {
    uint32_t r;
    asm("cvt.rna.tf32.f32 %0, %1;" : "=r"(r) : "f"(f));
    return r;
}
__device__ __forceinline__ void mma_tf32(float* d, const uint32_t* a, const uint32_t* b) {
    asm volatile(
        "mma.sync.aligned.m16n8k8.row.col.f32.tf32.tf32.f32 "
        "{%0,%1,%2,%3}, {%4,%5,%6,%7}, {%8,%9}, {%0,%1,%2,%3};"
        : "+f"(d[0]), "+f"(d[1]), "+f"(d[2]), "+f"(d[3])
        : "r"(a[0]), "r"(a[1]), "r"(a[2]), "r"(a[3]), "r"(b[0]), "r"(b[1]));
}

// ---- Shared-memory tile geometry ----
// A tile: 128 rows x 32 floats, XOR-swizzled (stride 32, no padding):
//   16B chunk `seg` (0..7) of row r stored at chunk slot (seg ^ (r&7)).
//   Fragment LDS bank = ((2ks[+1]) ^ g)*4 + tq -> 32 distinct banks.
// B tile: 32 rows x 128 floats, padded stride 136 -> bank (8tq+g)%32 distinct.
#define BSTR 136
#define NSTAGE 3
#define A_STG (128*32)              // floats per A stage (16384 B)
#define B_STG (32*BSTR)             // floats per B stage (17408 B)
#define SM_AS 512                                   // after s_tok[128]
#define SM_BS (SM_AS + NSTAGE*A_STG*4)              // 512 + 49152 = 49664
#define GEMM_SMEM (SM_BS + NSTAGE*B_STG*4)          // + 52224 = 101888 (<104KB -> 2 CTA/SM)

// ==================== reset counters (graph replays) ====================
__global__ void zero_kernel() {
    int i = threadIdx.x;
    if (i < EDIM) { g_freq[i] = 0; g_cursor[i] = 0; g_psum[i] = 0.f; }
    if (i == 0) g_lsesq = 0.f;
}

// ==================== router ====================
__global__ void router_kernel(const float* __restrict__ x,
                              const float* __restrict__ wr) {
    __shared__ float s_p[EDIM];
    __shared__ float s_lsesq;
    int tid = threadIdx.x;
    if (tid < EDIM) s_p[tid] = 0.f;
    if (tid == 0) s_lsesq = 0.f;
    __syncthreads();

    int t = blockIdx.x * 8 + (tid >> 5);
    int lane = tid & 31;

    float acc[8] = {0.f,0.f,0.f,0.f,0.f,0.f,0.f,0.f};
    const float* xp = x + (size_t)t * HDIM;
    for (int h = lane; h < HDIM; h += 32) {
        float xv = xp[h];
        float4 w0 = *(const float4*)(wr + h * 8);
        float4 w1 = *(const float4*)(wr + h * 8 + 4);
        acc[0] += xv * w0.x; acc[1] += xv * w0.y;
        acc[2] += xv * w0.z; acc[3] += xv * w0.w;
        acc[4] += xv * w1.x; acc[5] += xv * w1.y;
        acc[6] += xv * w1.z; acc[7] += xv * w1.w;
    }
#pragma unroll
    for (int e = 0; e < 8; e++)
#pragma unroll
        for (int o = 16; o > 0; o >>= 1)
            acc[e] += __shfl_down_sync(0xffffffffu, acc[e], o);

    if (lane == 0) {
        float m = acc[0];
#pragma unroll
        for (int e = 1; e < 8; e++) m = fmaxf(m, acc[e]);
        float ex[8], sum = 0.f;
#pragma unroll
        for (int e = 0; e < 8; e++) { ex[e] = expf(acc[e] - m); sum += ex[e]; }
        float inv = 1.f / sum;
        float lse = m + logf(sum);

        int i0 = 0;
#pragma unroll
        for (int e = 1; e < 8; e++) if (acc[e] > acc[i0]) i0 = e;
        int i1 = (i0 == 0) ? 1 : 0;
#pragma unroll
        for (int e = 0; e < 8; e++) if (e != i0 && acc[e] > acc[i1]) i1 = e;

        float d = expf(acc[i1] - acc[i0]);
        float g0 = 1.f / (1.f + d);
        float g1 = d / (1.f + d);

        g_eid[2 * t]     = i0;  g_eid[2 * t + 1]  = i1;
        g_gate[2 * t]    = g0;  g_gate[2 * t + 1] = g1;
        atomicAdd(&g_freq[i0], 1);
        atomicAdd(&g_freq[i1], 1);
#pragma unroll
        for (int e = 0; e < 8; e++) atomicAdd(&s_p[e], ex[e] * inv);
        atomicAdd(&s_lsesq, lse * lse);
    }
    __syncthreads();
    if (tid < EDIM) atomicAdd(&g_psum[tid], s_p[tid]);
    if (tid == 0)   atomicAdd(&g_lsesq, s_lsesq);
}

__global__ void scan_kernel() {
    if (threadIdx.x == 0) {
        int s = 0;
        for (int e = 0; e < EDIM; e++) { g_offsets[e] = s; s += g_freq[e]; }
        g_offsets[EDIM] = s;
    }
}

__global__ void scatter_kernel() {
    int r = blockIdx.x * blockDim.x + threadIdx.x;
    if (r < NROWS) {
        int e = g_eid[r];
        int pos = atomicAdd(&g_cursor[e], 1);
        g_list[g_offsets[e] + pos] = r;
    }
}

// ==================== tile loaders (128 threads) ====================
// A: 128 gathered rows x 32 K-floats (swizzled). B: 32 K-rows x 128 cols (padded).
__device__ __forceinline__ void g1_load(const float* __restrict__ x,
                                        const float* __restrict__ w1,
                                        const int* s_tok,
                                        uint32_t as_u, uint32_t bs_u,
                                        int tid, int n0, int c) {
    const int k0 = c * 32;
    const int st = c % NSTAGE;
#pragma unroll
    for (int i = 0; i < 8; i++) {
        int idx = tid + i * 128;
        int row = idx >> 3, seg = idx & 7;
        const float* src = x + (size_t)s_tok[row] * HDIM + k0 + seg * 4;
        int slot = seg ^ (row & 7);
        cp16(as_u + (uint32_t)((st * A_STG + row * 32 + slot * 4) * 4), src);
    }
#pragma unroll
    for (int i = 0; i < 8; i++) {
        int idx = tid + i * 128;
        int kr = idx >> 5, j = (idx & 31) * 4;
        int half = (j >> 5) & 1, blk = j >> 6, cloc = j & 31;
        int wcol = n0 + blk * 32 + cloc + (half ? FDIM : 0);
        const float* src = w1 + (size_t)(k0 + kr) * (2 * FDIM) + wcol;
        cp16(bs_u + (uint32_t)((st * B_STG + kr * BSTR + j) * 4), src);
    }
    CP_COMMIT();
}

__device__ __forceinline__ void g2_load(const float* __restrict__ w2,
                                        int off, int row0, int rlim,
                                        uint32_t as_u, uint32_t bs_u,
                                        int tid, int n1, int c) {
    const int k0 = c * 32;
    const int st = c % NSTAGE;
#pragma unroll
    for (int i = 0; i < 8; i++) {
        int idx = tid + i * 128;
        int row = idx >> 3, seg = idx & 7;
        int rr = (row < rlim) ? row : (rlim - 1);
        const float* src = g_glu + (size_t)(off + row0 + rr) * FDIM + k0 + seg * 4;
        int slot = seg ^ (row & 7);
        cp16(as_u + (uint32_t)((st * A_STG + row * 32 + slot * 4) * 4), src);
    }
#pragma unroll
    for (int i = 0; i < 8; i++) {
        int idx = tid + i * 128;
        int kr = idx >> 5, j = (idx & 31) * 4;
        const float* src = w2 + (size_t)(k0 + kr) * HDIM + n1 + j;
        cp16(bs_u + (uint32_t)((st * B_STG + kr * BSTR + j) * 4), src);
    }
    CP_COMMIT();
}

// compute one K-chunk (shared by both GEMMs). A swizzled, B padded.
__device__ __forceinline__ void chunk_mma(const float* Ast, const float* Bst,
                                          int wm, int wn, int g, int tq,
                                          float acc[4][8][4]) {
#pragma unroll
    for (int ks = 0; ks < 4; ks++) {
        const int sl0 = ((2 * ks) ^ g) * 4 + tq;       // col tq   within seg 2ks
        const int sl1 = ((2 * ks + 1) ^ g) * 4 + tq;   // col tq+4 within seg 2ks+1
        uint32_t af[4][4];
#pragma unroll
        for (int i = 0; i < 4; i++) {
            const float* ar = Ast + (wm * 64 + i * 16 + g) * 32;
            af[i][0] = f2tf32(ar[sl0]);
            af[i][1] = f2tf32(ar[8 * 32 + sl0]);
            af[i][2] = f2tf32(ar[sl1]);
            af[i][3] = f2tf32(ar[8 * 32 + sl1]);
        }
        uint32_t bf[8][2];
#pragma unroll
        for (int f = 0; f < 8; f++) {
            const float* bp = Bst + (ks * 8 + tq) * BSTR + wn * 64 + f * 8 + g;
            bf[f][0] = f2tf32(bp[0]);
            bf[f][1] = f2tf32(bp[4 * BSTR]);
        }
#pragma unroll
        for (int i = 0; i < 4; i++)
#pragma unroll
            for (int f = 0; f < 8; f++)
                mma_tf32(acc[i][f], af[i], bf[f]);
    }
}

// ==================== GEMM1: x[tok] @ w_in[e], fused GLU ====================
// CTA tile 128 rows x (64 a-cols + 64 gv-cols). 4 warps of 64x64.
// 3-stage cp.async pipeline, ONE barrier per chunk, loads issued before compute.
__global__ void __launch_bounds__(128) gemm1_mma(const float* __restrict__ x,
                                                 const float* __restrict__ w_in) {
    const int e = blockIdx.z;
    const int cnt = g_freq[e];
    const int row0 = blockIdx.y * 128;
    if (row0 >= cnt) return;
    const int off = g_offsets[e];
    const int n0 = blockIdx.x * 64;

    extern __shared__ char smem[];
    int* s_tok = (int*)smem;
    float* As = (float*)(smem + SM_AS);
    float* Bs = (float*)(smem + SM_BS);
    const uint32_t as_u = smem_u32(As), bs_u = smem_u32(Bs);

    const int tid = threadIdx.x;
    {
        int r = row0 + tid;
        s_tok[tid] = g_list[off + ((r < cnt) ? r : (cnt - 1))] >> 1;
    }
    __syncthreads();

    const float* w1 = w_in + (size_t)e * HDIM * (2 * FDIM);

    const int lane = tid & 31, wid = tid >> 5;
    const int wm = wid & 1, wn = wid >> 1;
    const int g = lane >> 2, tq = lane & 3;

    float acc[4][8][4];
#pragma unroll
    for (int i = 0; i < 4; i++)
#pragma unroll
        for (int f = 0; f < 8; f++)
#pragma unroll
            for (int q = 0; q < 4; q++) acc[i][f][q] = 0.f;

    const int NCH = HDIM / 32;  // 32
    g1_load(x, w1, s_tok, as_u, bs_u, tid, n0, 0);
    g1_load(x, w1, s_tok, as_u, bs_u, tid, n0, 1);

    for (int c = 0; c < NCH; c++) {
        if (c + 1 < NCH) CP_WAIT1(); else CP_WAIT0();   // stage c arrived
        __syncthreads();                                 // stage (c+2)%3 free
        if (c + 2 < NCH) g1_load(x, w1, s_tok, as_u, bs_u, tid, n0, c + 2);
        const int st = c % NSTAGE;
        chunk_mma(As + st * A_STG, Bs + st * B_STG, wm, wn, g, tq, acc);
    }

    // epilogue: GLU
#pragma unroll
    for (int i = 0; i < 4; i++) {
        const int rbase = wm * 64 + i * 16 + g;
#pragma unroll
        for (int hr = 0; hr < 2; hr++) {
            const int r = rbase + hr * 8;
            if (row0 + r < cnt) {
                float* dst = g_glu + (size_t)(off + row0 + r) * FDIM + n0 + wn * 32;
#pragma unroll
                for (int f = 0; f < 4; f++) {
                    float a0 = acc[i][f][hr * 2], a1 = acc[i][f][hr * 2 + 1];
                    float v0 = acc[i][f + 4][hr * 2], v1 = acc[i][f + 4][hr * 2 + 1];
                    float2 o;
                    o.x = (a0 / (1.f + __expf(-a0))) * v0;
                    o.y = (a1 / (1.f + __expf(-a1))) * v1;
                    *(float2*)(dst + f * 8 + 2 * tq) = o;
                }
            }
        }
    }
}

// ==================== GEMM2: glu @ w_out[e], fused gate-scale scatter ====================
__global__ void __launch_bounds__(128) gemm2_mma(const float* __restrict__ w_out) {
    const int e = blockIdx.z;
    const int cnt = g_freq[e];
    const int row0 = blockIdx.y * 128;
    if (row0 >= cnt) return;
    const int off = g_offsets[e];
    const int n1 = blockIdx.x * 128;
    const int rlim = cnt - row0;

    extern __shared__ char smem[];
    int* s_dst = (int*)smem;
    float* As = (float*)(smem + SM_AS);
    float* Bs = (float*)(smem + SM_BS);
    const uint32_t as_u = smem_u32(As), bs_u = smem_u32(Bs);

    const int tid = threadIdx.x;
    {
        int r = row0 + tid;
        s_dst[tid] = g_list[off + ((r < cnt) ? r : (cnt - 1))];
    }
    __syncthreads();

    const float* w2 = w_out + (size_t)e * FDIM * HDIM;

    const int lane = tid & 31, wid = tid >> 5;
    const int wm = wid & 1, wn = wid >> 1;
    const int g = lane >> 2, tq = lane & 3;

    float acc[4][8][4];
#pragma unroll
    for (int i = 0; i < 4; i++)
#pragma unroll
        for (int f = 0; f < 8; f++)
#pragma unroll
            for (int q = 0; q < 4; q++) acc[i][f][q] = 0.f;

    const int NCH = FDIM / 32;  // 64
    g2_load(w2, off, row0, rlim, as_u, bs_u, tid, n1, 0);
    g2_load(w2, off, row0, rlim, as_u, bs_u, tid, n1, 1);

    for (int c = 0; c < NCH; c++) {
        if (c + 1 < NCH) CP_WAIT1(); else CP_WAIT0();
        __syncthreads();
        if (c + 2 < NCH) g2_load(w2, off, row0, rlim, as_u, bs_u, tid, n1, c + 2);
        const int st = c % NSTAGE;
        chunk_mma(As + st * A_STG, Bs + st * B_STG, wm, wn, g, tq, acc);
    }

    // epilogue: scale by gate, scatter rows to g_pairs[dst]
#pragma unroll
    for (int i = 0; i < 4; i++) {
        const int rbase = wm * 64 + i * 16 + g;
#pragma unroll
        for (int hr = 0; hr < 2; hr++) {
            const int r = rbase + hr * 8;
            if (r < rlim) {
                const int dst = s_dst[r];
                const float gt = g_gate[dst];
                float* op = g_pairs + (size_t)dst * HDIM + n1 + wn * 64;
#pragma unroll
                for (int f = 0; f < 8; f++) {
                    float2 o;
                    o.x = acc[i][f][hr * 2] * gt;
                    o.y = acc[i][f][hr * 2 + 1] * gt;
                    *(float2*)(op + f * 8 + 2 * tq) = o;
                }
            }
        }
    }
}

// ==================== combine + loss ====================
__global__ void combine_kernel(float* __restrict__ out, const float* __restrict__ bias) {
    int i = blockIdx.x * blockDim.x + threadIdx.x;
    if (i < TDIM * HDIM / 4) {
        int t = i >> 8;
        int c4 = i & 255;
        const float4* p4 = (const float4*)g_pairs;
        float4 a = p4[(size_t)(2 * t) * 256 + c4];
        float4 b = p4[(size_t)(2 * t) * 256 + 256 + c4];
        float4 bs = ((const float4*)bias)[c4];
        float4 o;
        o.x = a.x + b.x + bs.x; o.y = a.y + b.y + bs.y;
        o.z = a.z + b.z + bs.z; o.w = a.w + b.w + bs.w;
        ((float4*)out)[i] = o;
    }
}

__global__ void loss_kernel(float* __restrict__ out, int out_size) {
    if (threadIdx.x == 0 && blockIdx.x == 0) {
        float s = 0.f;
        for (int e = 0; e < EDIM; e++) s += g_psum[e] * (float)g_freq[e];
        float loss = (float)EDIM * s / ((float)TDIM * (float)(TDIM * KSEL))
                   + 0.1f * g_lsesq / (float)TDIM;
        if (out_size > TDIM * HDIM) out[TDIM * HDIM] = loss;
    }
}

// ==================== launch ====================
extern "C" void kernel_launch(void* const* d_in, const int* in_sizes, int n_in,
                              void* d_out, int out_size) {
    const float* x        = (const float*)d_in[0];
    const float* w_router = (const float*)d_in[1];
    const float* w_in     = (const float*)d_in[2];
    const float* w_out    = (const float*)d_in[3];
    const float* bias     = (const float*)d_in[4];
    float* out = (float*)d_out;

    cudaFuncSetAttribute(gemm1_mma, cudaFuncAttributeMaxDynamicSharedMemorySize, GEMM_SMEM);
    cudaFuncSetAttribute(gemm2_mma, cudaFuncAttributeMaxDynamicSharedMemorySize, GEMM_SMEM);

    zero_kernel<<<1, 32>>>();
    router_kernel<<<TDIM / 8, 256>>>(x, w_router);
    scan_kernel<<<1, 32>>>();
    scatter_kernel<<<NROWS / 256, 256>>>();

    gemm1_mma<<<dim3(FDIM / 64, TDIM / 128, EDIM), 128, GEMM_SMEM>>>(x, w_in);
    gemm2_mma<<<dim3(HDIM / 128, TDIM / 128, EDIM), 128, GEMM_SMEM>>>(w_out);

    combine_kernel<<<(TDIM * HDIM / 4 + 255) / 256, 256>>>(out, bias);
    loss_kernel<<<1, 32>>>(out, out_size);
}